// round 13
// baseline (speedup 1.0000x reference)
#include <cuda_runtime.h>
#include <cuda_fp16.h>
#include <cstdint>

#define VSZ 20000
#define MM  32
#define EE  128
#define NN  8192
#define LL  64

typedef unsigned long long ull;

// ---------------- scratch (device globals; no allocation allowed) -----------
__device__ float g_Q[NN*EE];
__device__ float g_K[NN*EE];
__device__ float g_V[NN*EE];
__device__ float g_wemb[VSZ*EE];
// conv weights: 12 slices x 32KB fp16 [n=128][k=128], XOR-swizzled
__device__ uint4 g_WB[393216/16];

// ---------------- helpers ----------------------------------------------------
__device__ __forceinline__ uint32_t s2u(const void* p){
    return (uint32_t)__cvta_generic_to_shared(p);
}
__device__ __forceinline__ void cp16(uint32_t d, const void* s){
    asm volatile("cp.async.cg.shared.global [%0], [%1], 16;" :: "r"(d), "l"(s));
}
__device__ __forceinline__ void ldsm4(uint32_t* r, uint32_t addr){
    asm volatile("ldmatrix.sync.aligned.m8n8.x4.shared.b16 {%0,%1,%2,%3}, [%4];"
        : "=r"(r[0]), "=r"(r[1]), "=r"(r[2]), "=r"(r[3]) : "r"(addr));
}
__device__ __forceinline__ void mma16816(float* c, const uint32_t* a, const uint32_t* b){
    asm volatile("mma.sync.aligned.m16n8k16.row.col.f32.f16.f16.f32 "
        "{%0,%1,%2,%3}, {%4,%5,%6,%7}, {%8,%9}, {%0,%1,%2,%3};"
        : "+f"(c[0]), "+f"(c[1]), "+f"(c[2]), "+f"(c[3])
        : "r"(a[0]), "r"(a[1]), "r"(a[2]), "r"(a[3]), "r"(b[0]), "r"(b[1]));
}
__device__ __forceinline__ uint32_t f2h2(float a, float b){
    __half2 h = __floats2half2_rn(a, b);
    return *(uint32_t*)&h;
}

// ============================================================================
// Kernel 1: project news table: Qn/Kn/Vn = table @ W.T + b
// ============================================================================
__global__ void proj_kernel(const float* __restrict__ table,
                            const float* __restrict__ ipw,
                            const float* __restrict__ ipb){
    __shared__ float sX[8*EE];
    int tid = threadIdx.x;
    int n0 = blockIdx.x*8;
    for (int i = tid; i < 8*EE; i += 384)
        sX[i] = table[(size_t)(n0 + (i >> 7))*EE + (i & 127)];
    __syncthreads();

    int o = tid;                               // 0..383
    const float4* wr = (const float4*)(ipw + (size_t)o*EE);
    float acc[8];
    #pragma unroll
    for (int n = 0; n < 8; n++) acc[n] = 0.f;
    #pragma unroll 4
    for (int j = 0; j < 32; j++){
        float4 wv = wr[j];
        #pragma unroll
        for (int n = 0; n < 8; n++){
            float4 x = ((const float4*)(sX + n*EE))[j];
            acc[n] += wv.x*x.x + wv.y*x.y + wv.z*x.z + wv.w*x.w;
        }
    }
    float b = ipb[o];
    float* dst = (o < 128) ? g_Q : (o < 256) ? g_K : g_V;
    int col = o & 127;
    #pragma unroll
    for (int n = 0; n < 8; n++)
        dst[(size_t)(n0 + n)*EE + col] = acc[n] + b;
}

// ============================================================================
// Kernel 2: bake conv weights -> fp16, [slice][n][k] XOR-swizzled.
// ============================================================================
__global__ void wprep_kernel(const float* __restrict__ w3,
                             const float* __restrict__ w4,
                             const float* __restrict__ w5){
    int idx = blockIdx.x*256 + threadIdx.x;
    if (idx >= 196608) return;
    int s = idx >> 14, rem = idx & 16383;
    int n = rem >> 7, e = rem & 127;
    int k, j; const float* w;
    if (s < 3){ k = 3; j = s;     w = w3; }
    else if (s < 7){ k = 4; j = s - 3; w = w4; }
    else { k = 5; j = s - 7; w = w5; }
    __half h = __float2half_rn(w[(n*EE + e)*k + j]);
    int ck = e >> 3;
    int phys = (ck & 8) | ((ck & 7) ^ (n & 7));
    size_t base = (size_t)s*32768 + (size_t)n*256 + (size_t)phys*16 + (size_t)(e&7)*2;
    *(unsigned short*)((char*)g_WB + base) = __half_as_ushort(h);
}

// ============================================================================
// Kernel 3: per-word 1-query MHA using precomputed projected tables.
// ============================================================================
__global__ void attn_kernel(const int* __restrict__ w2n,
                            const int* __restrict__ w2nlen,
                            const float* __restrict__ opw,
                            const float* __restrict__ opb){
    int v = blockIdx.x, e = threadIdx.x;
    int h = e >> 5, lane = e & 31;
    int ln = w2nlen[v];
    if (ln == 0){ g_wemb[v*EE + e] = 0.f; return; }

    __shared__ int   sIdx[MM];
    __shared__ float sQ[EE], sAttn[EE], sO[EE];
    __shared__ float sK[MM*129];

    if (e < MM) sIdx[e] = (e < ln) ? w2n[v*MM + e] : 0;
    __syncthreads();

    float qa = 0.f;
    {
        int m = 0;
        for (; m + 2 <= ln; m += 2){
            int r0 = sIdx[m], r1 = sIdx[m+1];
            float q0 = g_Q[r0*EE + e], q1 = g_Q[r1*EE + e];
            sK[m*129 + e]     = g_K[r0*EE + e];
            sK[(m+1)*129 + e] = g_K[r1*EE + e];
            qa += q0 + q1;
        }
        if (m < ln){
            int r = sIdx[m];
            qa += g_Q[r*EE + e];
            sK[m*129 + e] = g_K[r*EE + e];
        }
    }
    sQ[e] = qa / (float)ln;
    __syncthreads();

    float s = -1e9f;
    if (lane < ln){
        s = 0.f;
        int base = h*32;
        #pragma unroll 8
        for (int d = 0; d < 32; d++)
            s += sQ[base + d] * sK[lane*129 + base + d];
        s *= 0.17677669529663687f;
    }
    float mx = s;
    #pragma unroll
    for (int o = 16; o > 0; o >>= 1) mx = fmaxf(mx, __shfl_xor_sync(0xffffffffu, mx, o));
    float ex = (lane < ln) ? __expf(s - mx) : 0.f;
    float sm = ex;
    #pragma unroll
    for (int o = 16; o > 0; o >>= 1) sm += __shfl_xor_sync(0xffffffffu, sm, o);
    sAttn[e] = ex / sm;
    __syncthreads();

    float oa = 0.f;
    {
        int m = 0;
        for (; m + 4 <= ln; m += 4){
            float a0 = sAttn[h*32 + m]     * g_V[sIdx[m]*EE + e];
            float a1 = sAttn[h*32 + m + 1] * g_V[sIdx[m+1]*EE + e];
            float a2 = sAttn[h*32 + m + 2] * g_V[sIdx[m+2]*EE + e];
            float a3 = sAttn[h*32 + m + 3] * g_V[sIdx[m+3]*EE + e];
            oa += (a0 + a1) + (a2 + a3);
        }
        for (; m < ln; m++)
            oa += sAttn[h*32 + m] * g_V[sIdx[m]*EE + e];
    }
    sO[e] = oa;
    __syncthreads();

    float r = opb[e];
    const float4* w4 = (const float4*)(opw + (size_t)e*EE);
    const float4* o4 = (const float4*)sO;
    #pragma unroll 8
    for (int j = 0; j < EE/4; j++){
        float4 w = w4[j]; float4 o = o4[j];
        r += w.x*o.x + w.y*o.y + w.z*o.z + w.w*o.w;
    }
    g_wemb[v*EE + e] = r;
}

// ============================================================================
// Kernel 4: fp16 mma.sync implicit-GEMM conv + relu + maxpool + fc.
// CTA = 4 docs: M=256 (doc*68-row layout), N=128. 8 warps, warp tile 64m x 64n
// (mb = warp>>1 selects doc, nb = warp&1 selects channel half).
// Per k16: 8 LDSM.x4 -> 32 MMAs per warp (tensor-bound, 2x crossbar headroom).
// Weights streamed per j-slice (32KB) double-buffered via cp.async.
// ============================================================================
#define SM_A    0                   // 272 rows * 272B = 73984
#define SM_W    73984               // 2 x 32768 ring -> 139520
#define SM_PART 139520              // 8 warps x 64 floats -> 141568
#define SM_POOL 141568              // 4 x 384 floats -> 147712
#define SM_TOT  147712

__global__ __launch_bounds__(256, 1)
void conv_kernel(const int*   __restrict__ nws,
                 const float* __restrict__ b3,
                 const float* __restrict__ b4,
                 const float* __restrict__ b5,
                 const float* __restrict__ fcw,
                 const float* __restrict__ fcb,
                 float*       __restrict__ out){
    extern __shared__ char shb[];
    float* shf = (float*)shb;
    const int bid = blockIdx.x, tid = threadIdx.x;
    const int w = tid >> 5, lane = tid & 31;
    const int mb = w >> 1, nb = w & 1;     // mb = doc 0..3, nb = n-half
    const uint32_t sb = s2u(shb);

    // ---- gather 4 docs (256 rows), convert to fp16 ----
    #pragma unroll
    for (int it = 0; it < 16; it++){
        int idx = tid + it*256;            // 256 rows x 16 octs
        int row = idx >> 4, oct = idx & 15;
        int wd = nws[bid*256 + row];
        const float4* s = (const float4*)(g_wemb + (size_t)wd*EE) + oct*2;
        float4 s0 = s[0], s1 = s[1];
        uint4 H;
        H.x = f2h2(s0.x, s0.y); H.y = f2h2(s0.z, s0.w);
        H.z = f2h2(s1.x, s1.y); H.w = f2h2(s1.z, s1.w);
        int srow = (row >> 6)*68 + (row & 63);
        *(uint4*)(shb + SM_A + srow*272 + oct*16) = H;
    }
    // zero-pad rows 64..67 of each doc
    for (int i = tid; i < 4*4*17; i += 256){
        int dd = i / 68, rem = i - dd*68;
        int r = rem / 17, c4 = rem % 17;
        int srow = dd*68 + 64 + r;
        *(uint4*)(shb + SM_A + srow*272 + c4*16) = make_uint4(0,0,0,0);
    }

    // ---- per-thread ldmatrix address precompute ----
    const int khalf = (lane >> 3) & 1;
    int n7[4]; uint32_t rbB[4];
    #pragma unroll
    for (int p = 0; p < 4; p++){
        int n = nb*64 + p*16 + (((lane >> 3) >= 2) ? 8 : 0) + (lane & 7);
        n7[p]  = n & 7;
        rbB[p] = (uint32_t)n * 256;
    }
    const uint32_t aBase = sb + SM_A
        + (uint32_t)(mb*68 + (lane & 15))*272 + (uint32_t)(lane >> 4)*16;

    // ---- prefetch slice 0 (32KB) ----
    {
        const char* src = (const char*)g_WB + tid*16;
        uint32_t dst = sb + SM_W + tid*16;
        #pragma unroll
        for (int q = 0; q < 8; q++) cp16(dst + q*4096, src + q*4096);
        asm volatile("cp.async.commit_group;");
    }

    float acc[4][8][4];
    float* part = shf + SM_PART/4;
    float* pool = shf + SM_POOL/4;

    int ci = 0;
    for (int kk = 0; kk < 3; kk++){
        const int Kk = kk + 3;
        #pragma unroll
        for (int mt = 0; mt < 4; mt++)
            #pragma unroll
            for (int nt = 0; nt < 8; nt++)
                #pragma unroll
                for (int i = 0; i < 4; i++) acc[mt][nt][i] = 0.f;

        for (int j = 0; j < Kk; j++, ci++){
            if (ci + 1 < 12){
                const char* src = (const char*)g_WB + (size_t)(ci+1)*32768 + tid*16;
                uint32_t dst = sb + SM_W + (uint32_t)((ci+1)&1)*32768 + tid*16;
                #pragma unroll
                for (int q = 0; q < 8; q++) cp16(dst + q*4096, src + q*4096);
                asm volatile("cp.async.commit_group;");
                asm volatile("cp.async.wait_group 1;");
            } else {
                asm volatile("cp.async.wait_group 0;");
            }
            __syncthreads();

            const uint32_t wbuf = sb + SM_W + (uint32_t)(ci & 1)*32768;
            const uint32_t aj = aBase + (uint32_t)j*272;

            #pragma unroll
            for (int ks = 0; ks < 8; ks++){
                uint32_t A[4][4];
                #pragma unroll
                for (int q = 0; q < 4; q++)
                    ldsm4(A[q], aj + (uint32_t)q*(16*272) + ks*32);
                uint32_t B[4][4];
                #pragma unroll
                for (int p = 0; p < 4; p++){
                    int ck = ks*2 + khalf;
                    int phys = (ck & 8) | ((ck & 7) ^ n7[p]);
                    ldsm4(B[p], wbuf + rbB[p] + (uint32_t)phys*16);
                }
                #pragma unroll
                for (int mt = 0; mt < 4; mt++){
                    #pragma unroll
                    for (int p = 0; p < 4; p++){
                        #pragma unroll
                        for (int h = 0; h < 2; h++)
                            mma16816(acc[mt][p*2 + h], A[mt], &B[p][h*2]);
                    }
                }
            }
            __syncthreads();
        }

        // ---- epilogue: masked max over this doc's t rows ----
        const float* bias = (kk == 0) ? b3 : (kk == 1) ? b4 : b5;
        #pragma unroll
        for (int nt = 0; nt < 8; nt++){
            float m0 = -3.4e38f, m1 = -3.4e38f;
            #pragma unroll
            for (int mt = 0; mt < 4; mt++){
                int tb = mt*16 + (lane >> 2);
                if (tb <= LL - Kk){
                    m0 = fmaxf(m0, acc[mt][nt][0]);
                    m1 = fmaxf(m1, acc[mt][nt][1]);
                }
                if (tb + 8 <= LL - Kk){
                    m0 = fmaxf(m0, acc[mt][nt][2]);
                    m1 = fmaxf(m1, acc[mt][nt][3]);
                }
            }
            #pragma unroll
            for (int s = 4; s < 32; s <<= 1){
                m0 = fmaxf(m0, __shfl_xor_sync(0xffffffffu, m0, s));
                m1 = fmaxf(m1, __shfl_xor_sync(0xffffffffu, m1, s));
            }
            if (lane < 4){
                part[w*64 + nt*8 + (lane & 3)*2 + 0] = m0;
                part[w*64 + nt*8 + (lane & 3)*2 + 1] = m1;
            }
        }
        __syncthreads();
        #pragma unroll
        for (int it = 0; it < 2; it++){
            int g = tid + it*256;              // 0..511: 4 docs x 128 cols
            int dd = g >> 7, col = g & 127;
            float v = part[(dd*2 + (col >> 6))*64 + (col & 63)];
            // max_t relu(y+b) == relu(b + max_t y)
            pool[dd*384 + kk*128 + col] = fmaxf(v + bias[col], 0.f);
        }
        __syncthreads();
    }

    // ---- fc: out[n][e] = fc_b[e] + pooled . fc_w[e] ----
    #pragma unroll
    for (int it = 0; it < 2; it++){
        int g = tid + it*256;
        int dd = g >> 7, e = g & 127;
        float a = fcb[e];
        const float4* w4 = (const float4*)(fcw + (size_t)e*384);
        const float4* p4 = (const float4*)(pool + dd*384);
        #pragma unroll 8
        for (int r = 0; r < 96; r++){
            float4 ww = w4[r]; float4 pp = p4[r];
            a += ww.x*pp.x + ww.y*pp.y + ww.z*pp.z + ww.w*pp.w;
        }
        out[(size_t)(4*bid + dd)*EE + e] = a;
    }
}

// ============================================================================
extern "C" void kernel_launch(void* const* d_in, const int* in_sizes, int n_in,
                              void* d_out, int out_size){
    const int*   w2n   = (const int*)  d_in[0];
    const int*   w2nl  = (const int*)  d_in[1];
    const int*   nws   = (const int*)  d_in[2];
    const float* table = (const float*)d_in[3];
    const float* ipw   = (const float*)d_in[4];
    const float* ipb   = (const float*)d_in[5];
    const float* opw   = (const float*)d_in[6];
    const float* opb   = (const float*)d_in[7];
    const float* w3    = (const float*)d_in[8];
    const float* b3    = (const float*)d_in[9];
    const float* w4    = (const float*)d_in[10];
    const float* b4    = (const float*)d_in[11];
    const float* w5    = (const float*)d_in[12];
    const float* b5    = (const float*)d_in[13];
    const float* fcw   = (const float*)d_in[14];
    const float* fcb   = (const float*)d_in[15];
    float* out = (float*)d_out;

    cudaFuncSetAttribute(conv_kernel,
                         cudaFuncAttributeMaxDynamicSharedMemorySize, SM_TOT);

    proj_kernel <<<NN/8, 384>>>(table, ipw, ipb);
    wprep_kernel<<<768, 256>>>(w3, w4, w5);
    attn_kernel <<<VSZ, 128>>>(w2n, w2nl, opw, opb);
    conv_kernel <<<NN/4, 256, SM_TOT>>>(nws, b3, b4, b5, fcw, fcb, out);
}